// round 16
// baseline (speedup 1.0000x reference)
#include <cuda_runtime.h>
#include <cuda_fp16.h>
#include <math.h>
#include <stdint.h>

// Problem constants
#define Dd 32
#define Hh 1024
#define Ll 2
#define Bb 4096
#define BMs 32
#define NCTA 128
#define NT 512

typedef __half fp16;

// ---------------- device scratch (static, no allocation) ----------------
// Packed activation layout: [cta][kchunk 32][row 32][32 k] with 16B-swizzle
// q' = (kk>>3) ^ ((row>>1)&3); element = chunk*1024 + row*32 + q'*8 + (kk&7)
__device__ fp16  g_p0p[NCTA * 32 * 1024];   // packed fp16(relu(pre0))
__device__ fp16  g_a1p[NCTA * 32 * 1024];   // packed layer-1 activations
// Packed weights (single fp16): per (layer l, window jw 0..30, kchunk kc 0..31):
// 4KB tile = 64 rows x 32 k, swizzled like activations. kc-contiguous.
__device__ fp16  g_Whp[2 * 31 * 32 * 2048];
__device__ float g_bhs[Ll * Hh];
__device__ float g_W0r[Hh * Dd];            // masked sorted W0, row-major [t][j]
__device__ float g_b0s[Hh];                 // permuted b0
__device__ float g_WosT[Hh * 2 * Dd];       // masked output weights TRANSPOSED [t][o]

// Degree-sorted permutation. Hidden degree of original unit i is i % 31.
__device__ __forceinline__ int permS(int s) {
    return (s < 34) ? 31 * s : ((s - 1) / 33) + 31 * ((s - 1) % 33);
}
__device__ __forceinline__ int degS(int s) {
    return (s < 34) ? 0 : (s - 1) / 33;
}

// ---------------- weight pre-transform ----------------
__global__ void prep_kernel(const float* __restrict__ W0,
                            const float* __restrict__ b0,
                            const float* __restrict__ Wh,
                            const float* __restrict__ bh,
                            const float* __restrict__ Wout) {
    int stride = gridDim.x * blockDim.x;
    int tid0 = blockIdx.x * blockDim.x + threadIdx.x;

    for (int i = tid0; i < 2 * 31 * 32 * 2048; i += stride) {
        int l = i / 2031616;
        int r1 = i % 2031616;
        int jw = r1 >> 16;
        int r2 = r1 & 65535;
        int kc = r2 >> 11;
        int r3 = r2 & 2047;
        int row = r3 >> 5;
        int kk = r3 & 31;
        int s = jw * 32 + row;
        int t = kc * 32 + kk;
        float v = 0.f;
        if (degS(s) >= degS(t)) v = Wh[l * Hh * Hh + permS(s) * Hh + permS(t)];
        int base = ((l * 31 + jw) * 32 + kc) * 2048;
        int off = row * 32 + (((kk >> 3) ^ ((row >> 1) & 3)) << 3) + (kk & 7);
        g_Whp[base + off] = __float2half_rn(v);
    }
    for (int i = tid0; i < Ll * Hh; i += stride) {
        int l = i >> 10;
        int s = i & (Hh - 1);
        g_bhs[i] = bh[l * Hh + permS(s)];
    }
    for (int i = tid0; i < Hh * Dd; i += stride) {
        int t = i >> 5;
        int j = i & 31;
        g_W0r[i] = (degS(t) >= j) ? W0[permS(t) * Dd + j] : 0.f;
    }
    for (int i = tid0; i < Hh; i += stride) g_b0s[i] = b0[permS(i)];
    // output weights masked, TRANSPOSED: [t][o], o in 0..63
    for (int i = tid0; i < Hh * 2 * Dd; i += stride) {
        int t = i >> 6;
        int o = i & 63;
        g_WosT[i] = (((o & 31) - 1) >= degS(t)) ? Wout[o * Hh + permS(t)] : 0.f;
    }
}

// ---------------- smem layout (bytes) ----------------
// 4 bulk stages @0, each 128-k (4 chunks): {A 8192 | W 16384} = 24576
// p0 window @98304, a1 window @102400 : 2 chunks x 2048 B each
// a2 window @106496 : [32][65] fp32 (8320 B)
// acc       @114816 : [32][64] fp32 (8192 B) running mu/ls accumulators
// xs        @123008 : [32][33] fp32 (4224 B)
// mbars     @127232 : 4 x 8 B
#define STGB 24576
#define P0W_OFF 98304
#define A1W_OFF 102400
#define A2W_OFF 106496
#define ACC_OFF 114816
#define XS_OFF 123008
#define MBAR_OFF 127232
#define SMEMB 127488

__device__ __forceinline__ uint32_t smem_u32(const void* p) {
    return (uint32_t)__cvta_generic_to_shared(p);
}
__device__ __forceinline__ void cpbulk(uint32_t dst, const void* src,
                                       uint32_t bytes, uint32_t mbar) {
    asm volatile(
        "cp.async.bulk.shared::cta.global.mbarrier::complete_tx::bytes "
        "[%0], [%1], %2, [%3];\n"
        :: "r"(dst), "l"(src), "r"(bytes), "r"(mbar) : "memory");
}
__device__ __forceinline__ void mbar_init(uint32_t a, uint32_t cnt) {
    asm volatile("mbarrier.init.shared.b64 [%0], %1;" :: "r"(a), "r"(cnt) : "memory");
}
__device__ __forceinline__ void mbar_expect(uint32_t a, uint32_t bytes) {
    asm volatile("mbarrier.arrive.expect_tx.shared.b64 _, [%0], %1;"
                 :: "r"(a), "r"(bytes) : "memory");
}
__device__ __forceinline__ void mbar_wait(uint32_t mbar, uint32_t parity) {
    asm volatile(
        "{\n\t"
        ".reg .pred P;\n\t"
        "LW%=:\n\t"
        "mbarrier.try_wait.parity.acquire.cta.shared::cta.b64 P, [%0], %1, 0x989680;\n\t"
        "@P bra LD%=;\n\t"
        "bra LW%=;\n\t"
        "LD%=:\n\t"
        "}"
        :: "r"(mbar), "r"(parity) : "memory");
}
__device__ __forceinline__ void ldsm4(uint32_t& r0, uint32_t& r1, uint32_t& r2,
                                      uint32_t& r3, uint32_t addr) {
    asm volatile("ldmatrix.sync.aligned.m8n8.x4.shared.b16 {%0,%1,%2,%3}, [%4];\n"
                 : "=r"(r0), "=r"(r1), "=r"(r2), "=r"(r3) : "r"(addr));
}
__device__ __forceinline__ void mma_fp16(float c[4], const uint32_t a[4], const uint32_t b[2]) {
    asm volatile(
        "mma.sync.aligned.m16n8k16.row.col.f32.f16.f16.f32 "
        "{%0,%1,%2,%3}, {%4,%5,%6,%7}, {%8,%9}, {%0,%1,%2,%3};\n"
        : "+f"(c[0]), "+f"(c[1]), "+f"(c[2]), "+f"(c[3])
        : "r"(a[0]), "r"(a[1]), "r"(a[2]), "r"(a[3]), "r"(b[0]), "r"(b[1]));
}

// ---------------- window GEMM: out[32 rows, 64 cols @ wa] ----------------
// 128-k stages (4 chunks each): A packed chunks (bulk) or smem window for
// kc >= winStart; W packed 4KB tiles, ONE bulk per stage.
// 4-stage mbarrier ring, fetch-ahead 3, barrier-before-issue.
// Two accumulator chains (even/odd sub-chunk) halve the MMA dependency depth.
__device__ __forceinline__ void gemm_phase(
    uint32_t smemBase, uint32_t mbarBase, int& u,
    uint32_t winU, int winStart,
    int wa, int kend,
    const fp16* __restrict__ A_gp,      // packed A base for this CTA
    const fp16* __restrict__ B_gp,      // packed W base for (layer, window)
    const float* __restrict__ bias, int outSplit,
    fp16* __restrict__ gA1p,
    fp16* a1w, float* a2w, int cta) {

    const int tid = (int)threadIdx.x;
    const int lane = tid & 31;
    const int wid = tid >> 5;
    const int wm = wid & 1;       // 2 x m16
    const int wn = wid >> 1;      // 8 x n8
    const int lrow = lane & 15;

    float c0[4] = {0.f, 0.f, 0.f, 0.f};
    float c1[4] = {0.f, 0.f, 0.f, 0.f};
    const int nIter = (kend + 127) >> 7;
    const int u0 = u;

    auto issueStage = [&](int j) {
        int k0 = j * 128;
        int stage = (u0 + j) & 3;
        uint32_t mbar = mbarBase + stage * 8;
        uint32_t dstA = smemBase + (uint32_t)stage * STGB;
        int kA = (winStart - k0) >> 5;           // #A chunks to copy (prefix)
        if (kA < 0) kA = 0; if (kA > 4) kA = 4;
        int rem = (kend - k0) >> 5;
        if (rem > 4) rem = 4;
        if (kA > rem) kA = rem;
        uint32_t bytes = (uint32_t)kA * 2048u + (uint32_t)rem * 4096u;
        mbar_expect(mbar, bytes);
        if (kA)
            cpbulk(dstA, A_gp + (size_t)(k0 >> 5) * 1024, (uint32_t)kA * 2048u, mbar);
        cpbulk(dstA + 8192u, B_gp + (size_t)(k0 >> 5) * 2048, (uint32_t)rem * 4096u, mbar);
    };

    if (tid == 0) {
        for (int j = 0; j < 3 && j < nIter; j++) issueStage(j);
    }

    // ldsm lane addressing (packed/swizzled layout)
    const int aRow = wm * 16 + lrow;
    const int aSw = (aRow >> 1) & 3;
    const int bRow = wn * 8 + (lane & 7);
    const uint32_t bOff = (uint32_t)(bRow * 64 + (((lane >> 3) ^ ((bRow >> 1) & 3)) << 4));

    for (int it = 0; it < nIter; it++) {
        __syncthreads();
        if (tid == 0 && it + 3 < nIter) issueStage(it + 3);
        const int stage = (u0 + it) & 3;
        mbar_wait(mbarBase + stage * 8, (uint32_t)(((u0 + it) >> 2) & 1));

        const uint32_t sb = smemBase + (uint32_t)stage * STGB;
        const int k0 = it * 128;

#pragma unroll
        for (int sub = 0; sub < 4; sub++) {
            const int kc = k0 + sub * 32;
            if (kc < kend) {
                uint32_t aBase;
                if (kc >= winStart) {
                    aBase = winU + (uint32_t)((kc - winStart) >> 5) * 2048u;
                } else {
                    aBase = sb + (uint32_t)sub * 2048u;
                }
                const uint32_t wB = sb + 8192u + (uint32_t)sub * 4096u;

                uint32_t bh[4];
                ldsm4(bh[0], bh[1], bh[2], bh[3], wB + bOff);
                float* acc = (sub & 1) ? c1 : c0;

#pragma unroll
                for (int kst = 0; kst < 2; kst++) {
                    const int q = kst * 2 + (lane >> 4);
                    const uint32_t aoff = (uint32_t)(aRow * 64 + ((q ^ aSw) << 4));
                    uint32_t a[4];
                    ldsm4(a[0], a[1], a[2], a[3], aBase + aoff);
                    mma_fp16(acc, a, &bh[kst * 2]);
                }
            }
        }
    }
    u = u0 + nIter;

    // ---- epilogue: 4 outputs per warp ----
    const int r0 = wm * 16 + (lane >> 2);
    const int tg = lane & 3;
#pragma unroll
    for (int q = 0; q < 2; q++) {
        int cl = wn * 8 + tg * 2 + q;     // 0..63 window-local col
        int col = wa + cl;
        float bv = bias[col];
        float y0 = fmaxf(c0[q] + c1[q] + bv, 0.f);           // row r0
        float y1 = fmaxf(c0[q + 2] + c1[q + 2] + bv, 0.f);   // row r0+8
        if (outSplit) {
            fp16 h0 = __float2half_rn(y0);
            fp16 h1 = __float2half_rn(y1);
            int kk = col & 31;
            int qp = (kk >> 3) ^ ((r0 >> 1) & 3);
            int eg = ((cta * 32 + (col >> 5)) * 32) * 32;
            int e0 = eg + r0 * 32 + qp * 8 + (kk & 7);
            gA1p[e0] = h0;
            gA1p[e0 + 8 * 32] = h1;
            int ew = ((cl >> 5) * 32 + r0) * 32 + qp * 8 + (kk & 7);
            a1w[ew] = h0;
            a1w[ew + 8 * 32] = h1;
        } else {
            a2w[r0 * 65 + cl] = y0;
            a2w[(r0 + 8) * 65 + cl] = y1;
        }
    }
}

// ---------------- lazy pre0 materialization: cols [msA, msA+64) ----------------
__device__ __forceinline__ void materialize(const float* xs, int cta, int msA,
                                            int idx, fp16* p0w) {
    const int tid = (int)threadIdx.x;
    for (int i = tid; i < 2048; i += NT) {
        int r = i & 31;
        int t = msA + (i >> 5);
        const float* wr = g_W0r + t * Dd;
        float acc = g_b0s[t];
        for (int j = 0; j < idx; j++) acc = fmaf(wr[j], xs[r * 33 + j], acc);
        float y = fmaxf(acc, 0.f);
        fp16 hv = __float2half_rn(y);
        int kk = t & 31;
        int qp = (kk >> 3) ^ ((r >> 1) & 3);
        g_p0p[((cta * 32 + (t >> 5)) * 32 + r) * 32 + qp * 8 + (kk & 7)] = hv;
        int cl = t - msA;
        p0w[((cl >> 5) * 32 + r) * 32 + qp * 8 + (kk & 7)] = hv;
    }
}

// ---------------- finish: acc update (new cols only) + outputs ----------------
// acc[r][o] = sum over materialized a2 cols c of a2[r][c] * WosT[c][o].
// Each step adds cols [hPrev, h) from the smem a2 window.
__device__ __forceinline__ void finish_phase(const float* __restrict__ z,
                                             const float* __restrict__ bout,
                                             float* __restrict__ x,
                                             const float* a2w, float* accS,
                                             float* xs,
                                             int m0, int idx, int h, int hPrev,
                                             int wa) {
    const int tid = (int)threadIdx.x;
    // --- accumulate new columns' contribution to all 64 outputs ---
    if (h > hPrev) {
#pragma unroll
        for (int k = 0; k < 4; k++) {
            int p = tid + k * NT;          // 0..2047
            int o = p & 63;
            int r = p >> 6;                // 0..31
            float s = 0.f;
            for (int c = hPrev; c < h; c++)
                s = fmaf(a2w[r * 65 + (c - wa)], g_WosT[c * 64 + o], s);
            accS[r * 64 + o] += s;
        }
    }
    __syncthreads();

    // --- outputs: warp w handles rows 2w, 2w+1 ---
    const int wid = tid >> 5;
    const int lane = tid & 31;
#pragma unroll
    for (int rr = 0; rr < 2; rr++) {
        int r = wid * 2 + rr;
        if (lane == 0) {
            int row = m0 + r;
            float mu = accS[r * 64 + idx] + bout[idx];
            float ls = accS[r * 64 + idx + Dd] + bout[idx + Dd];
            float xi = z[(size_t)row * Dd + idx] * expf(ls) + mu;
            x[(size_t)row * Dd + idx] = xi;
            xs[r * 33 + idx] = xi;
        }
    }
}

// ---------------- persistent-per-CTA 32-step loop (no inter-CTA sync) -------
__global__ __launch_bounds__(NT, 1) void step_kernel(const float* __restrict__ z,
                                                     const float* __restrict__ bout,
                                                     float* __restrict__ x) {
    extern __shared__ char smraw[];
    const uint32_t smemBase = smem_u32(smraw);
    const uint32_t mbarBase = smemBase + MBAR_OFF;
    fp16* p0w = (fp16*)(smraw + P0W_OFF);
    fp16* a1w = (fp16*)(smraw + A1W_OFF);
    float* a2w = (float*)(smraw + A2W_OFF);
    float* accS = (float*)(smraw + ACC_OFF);
    float* xs = (float*)(smraw + XS_OFF);
    const int cta = (int)blockIdx.x;
    const int m0 = cta * BMs;

    if (threadIdx.x == 0) {
        for (int s = 0; s < 4; s++) mbar_init(mbarBase + s * 8, 1);
    }
    for (int i = threadIdx.x; i < 32 * 64; i += NT) accS[i] = 0.f;
    __syncthreads();

    int u = 0;   // persistent stage-use counter (stage = u&3, parity = (u>>2)&1)

    for (int idx = 0; idx < Dd; idx++) {
        const int h = idx ? (33 * idx + 1) : 0;
        const int hPrev = (idx > 1) ? (33 * (idx - 1) + 1) : 0;
        int wa = 0;
        if (idx) {
            const int msA = hPrev & ~31;
            const int kend1 = msA + 64;        // == (h+31)&~31
            materialize(xs, cta, msA, idx, p0w);
            __syncthreads();
            wa = (h - 33) & ~31;
            if (wa > 960) wa = 960;
            const int jw = wa >> 5;
            // layer 1: A = packed p0 (prefix bulk, fresh cols from p0 window)
            gemm_phase(smemBase, mbarBase, u, smem_u32(p0w), msA,
                       wa, kend1,
                       g_p0p + (size_t)cta * 32768,
                       g_Whp + (size_t)jw * 32 * 2048,
                       g_bhs, 1, g_a1p, a1w, a2w, cta);
            __syncthreads();
            // layer 2: A = packed a1 (prefix bulk, fresh window in smem)
            gemm_phase(smemBase, mbarBase, u, smem_u32(a1w), wa,
                       wa, wa + 64,
                       g_a1p + (size_t)cta * 32768,
                       g_Whp + (size_t)(31 + jw) * 32 * 2048,
                       g_bhs + Hh, 0, nullptr, a1w, a2w, cta);
            __syncthreads();
        }
        finish_phase(z, bout, x, a2w, accS, xs, m0, idx, h, hPrev, wa);
        __syncthreads();
    }
}

// ---------------- launch ----------------
extern "C" void kernel_launch(void* const* d_in, const int* in_sizes, int n_in,
                              void* d_out, int out_size) {
    const float* z    = (const float*)d_in[0];
    const float* W0   = (const float*)d_in[1];
    const float* b0   = (const float*)d_in[2];
    const float* Wh   = (const float*)d_in[3];
    const float* bh   = (const float*)d_in[4];
    const float* Wout = (const float*)d_in[5];
    const float* bout = (const float*)d_in[6];
    float* x = (float*)d_out;

    static int attrSet = 0;
    if (!attrSet) {
        cudaFuncSetAttribute(step_kernel, cudaFuncAttributeMaxDynamicSharedMemorySize,
                             SMEMB);
        attrSet = 1;
    }

    prep_kernel<<<1024, 256>>>(W0, b0, Wh, bh, Wout);
    step_kernel<<<NCTA, NT, SMEMB>>>(z, bout, x);
}

// round 17
// speedup vs baseline: 1.1485x; 1.1485x over previous
#include <cuda_runtime.h>
#include <cuda_fp16.h>
#include <math.h>
#include <stdint.h>

// Problem constants
#define Dd 32
#define Hh 1024
#define Ll 2
#define Bb 4096
#define BMs 16
#define NCTA 256
#define NT 256

typedef __half fp16;

// ---------------- device scratch (static, no allocation) ----------------
// Packed activation layout: [cta][kchunk 32][row 16][32 k] with 16B-swizzle
// q' = (kk>>3) ^ ((row>>1)&3); element = chunk*512 + row*32 + q'*8 + (kk&7)
__device__ fp16  g_p0p[NCTA * 32 * 512];    // packed fp16(relu(pre0))
__device__ fp16  g_a1p[NCTA * 32 * 512];    // packed layer-1 activations
// Packed weights (single fp16): per (layer l, window jw 0..30, kchunk kc 0..31):
// 4KB tile = 64 rows x 32 k, swizzled like activations. kc-contiguous.
__device__ fp16  g_Whp[2 * 31 * 32 * 2048];
__device__ float g_bhs[Ll * Hh];
__device__ float g_W0r[Hh * Dd];            // masked sorted W0, row-major [t][j]
__device__ float g_b0s[Hh];                 // permuted b0
__device__ float g_WosT[Hh * 2 * Dd];       // masked output weights TRANSPOSED [t][o]

// Degree-sorted permutation. Hidden degree of original unit i is i % 31.
__device__ __forceinline__ int permS(int s) {
    return (s < 34) ? 31 * s : ((s - 1) / 33) + 31 * ((s - 1) % 33);
}
__device__ __forceinline__ int degS(int s) {
    return (s < 34) ? 0 : (s - 1) / 33;
}

// ---------------- weight pre-transform ----------------
__global__ void prep_kernel(const float* __restrict__ W0,
                            const float* __restrict__ b0,
                            const float* __restrict__ Wh,
                            const float* __restrict__ bh,
                            const float* __restrict__ Wout) {
    int stride = gridDim.x * blockDim.x;
    int tid0 = blockIdx.x * blockDim.x + threadIdx.x;

    for (int i = tid0; i < 2 * 31 * 32 * 2048; i += stride) {
        int l = i / 2031616;
        int r1 = i % 2031616;
        int jw = r1 >> 16;
        int r2 = r1 & 65535;
        int kc = r2 >> 11;
        int r3 = r2 & 2047;
        int row = r3 >> 5;
        int kk = r3 & 31;
        int s = jw * 32 + row;
        int t = kc * 32 + kk;
        float v = 0.f;
        if (degS(s) >= degS(t)) v = Wh[l * Hh * Hh + permS(s) * Hh + permS(t)];
        int base = ((l * 31 + jw) * 32 + kc) * 2048;
        int off = row * 32 + (((kk >> 3) ^ ((row >> 1) & 3)) << 3) + (kk & 7);
        g_Whp[base + off] = __float2half_rn(v);
    }
    for (int i = tid0; i < Ll * Hh; i += stride) {
        int l = i >> 10;
        int s = i & (Hh - 1);
        g_bhs[i] = bh[l * Hh + permS(s)];
    }
    for (int i = tid0; i < Hh * Dd; i += stride) {
        int t = i >> 5;
        int j = i & 31;
        g_W0r[i] = (degS(t) >= j) ? W0[permS(t) * Dd + j] : 0.f;
    }
    for (int i = tid0; i < Hh; i += stride) g_b0s[i] = b0[permS(i)];
    for (int i = tid0; i < Hh * 2 * Dd; i += stride) {
        int t = i >> 6;
        int o = i & 63;
        g_WosT[i] = (((o & 31) - 1) >= degS(t)) ? Wout[o * Hh + permS(t)] : 0.f;
    }
}

// ---------------- smem layout (bytes) ----------------
// 4 bulk stages @0, each 128-k (4 chunks): {A 4096 (4x1KB) | W 16384} = 20480
// p0 window @81920, a1 window @83968 : 2 chunks x 1024 B each
// a2 window @86016 : [16][65] fp32 (4160 B)
// acc       @90176 : [16][64] fp32 (4096 B) running mu/ls accumulators
// xs        @94272 : [16][33] fp32 (2112 B)
// mbars     @96384 : 4 x 8 B
#define STGB 20480
#define P0W_OFF 81920
#define A1W_OFF 83968
#define A2W_OFF 86016
#define ACC_OFF 90176
#define XS_OFF 94272
#define MBAR_OFF 96384
#define SMEMB 96640

__device__ __forceinline__ uint32_t smem_u32(const void* p) {
    return (uint32_t)__cvta_generic_to_shared(p);
}
__device__ __forceinline__ void cpbulk(uint32_t dst, const void* src,
                                       uint32_t bytes, uint32_t mbar) {
    asm volatile(
        "cp.async.bulk.shared::cta.global.mbarrier::complete_tx::bytes "
        "[%0], [%1], %2, [%3];\n"
        :: "r"(dst), "l"(src), "r"(bytes), "r"(mbar) : "memory");
}
__device__ __forceinline__ void mbar_init(uint32_t a, uint32_t cnt) {
    asm volatile("mbarrier.init.shared.b64 [%0], %1;" :: "r"(a), "r"(cnt) : "memory");
}
__device__ __forceinline__ void mbar_expect(uint32_t a, uint32_t bytes) {
    asm volatile("mbarrier.arrive.expect_tx.shared.b64 _, [%0], %1;"
                 :: "r"(a), "r"(bytes) : "memory");
}
__device__ __forceinline__ void mbar_wait(uint32_t mbar, uint32_t parity) {
    asm volatile(
        "{\n\t"
        ".reg .pred P;\n\t"
        "LW%=:\n\t"
        "mbarrier.try_wait.parity.acquire.cta.shared::cta.b64 P, [%0], %1, 0x989680;\n\t"
        "@P bra LD%=;\n\t"
        "bra LW%=;\n\t"
        "LD%=:\n\t"
        "}"
        :: "r"(mbar), "r"(parity) : "memory");
}
__device__ __forceinline__ void ldsm4(uint32_t& r0, uint32_t& r1, uint32_t& r2,
                                      uint32_t& r3, uint32_t addr) {
    asm volatile("ldmatrix.sync.aligned.m8n8.x4.shared.b16 {%0,%1,%2,%3}, [%4];\n"
                 : "=r"(r0), "=r"(r1), "=r"(r2), "=r"(r3) : "r"(addr));
}
__device__ __forceinline__ void mma_fp16(float c[4], const uint32_t a[4], const uint32_t b[2]) {
    asm volatile(
        "mma.sync.aligned.m16n8k16.row.col.f32.f16.f16.f32 "
        "{%0,%1,%2,%3}, {%4,%5,%6,%7}, {%8,%9}, {%0,%1,%2,%3};\n"
        : "+f"(c[0]), "+f"(c[1]), "+f"(c[2]), "+f"(c[3])
        : "r"(a[0]), "r"(a[1]), "r"(a[2]), "r"(a[3]), "r"(b[0]), "r"(b[1]));
}

// ---------------- window GEMM: out[16 rows, 64 cols @ wa] ----------------
// 8 warps: warp w handles n8 tile wn=w, full m16. 128-k stages (4 chunks).
// A packed 1KB chunks (bulk) or smem window for kc >= winStart; W packed 4KB
// tiles. 4-stage mbarrier ring, fetch-ahead 3, barrier-before-issue.
__device__ __forceinline__ void gemm_phase(
    uint32_t smemBase, uint32_t mbarBase, int& u,
    uint32_t winU, int winStart,
    int wa, int kend,
    const fp16* __restrict__ A_gp,      // packed A base for this CTA
    const fp16* __restrict__ B_gp,      // packed W base for (layer, window)
    const float* __restrict__ bias, int outSplit,
    fp16* __restrict__ gA1p,
    fp16* a1w, float* a2w, int cta) {

    const int tid = (int)threadIdx.x;
    const int lane = tid & 31;
    const int wn = tid >> 5;      // 8 x n8
    const int lrow = lane & 15;

    float c0[4] = {0.f, 0.f, 0.f, 0.f};
    float c1[4] = {0.f, 0.f, 0.f, 0.f};
    const int nIter = (kend + 127) >> 7;
    const int u0 = u;

    auto issueStage = [&](int j) {
        int k0 = j * 128;
        int stage = (u0 + j) & 3;
        uint32_t mbar = mbarBase + stage * 8;
        uint32_t dstA = smemBase + (uint32_t)stage * STGB;
        int kA = (winStart - k0) >> 5;           // #A chunks to copy (prefix)
        if (kA < 0) kA = 0; if (kA > 4) kA = 4;
        int rem = (kend - k0) >> 5;
        if (rem > 4) rem = 4;
        if (kA > rem) kA = rem;
        uint32_t bytes = (uint32_t)kA * 1024u + (uint32_t)rem * 4096u;
        mbar_expect(mbar, bytes);
        if (kA)
            cpbulk(dstA, A_gp + (size_t)(k0 >> 5) * 512, (uint32_t)kA * 1024u, mbar);
        cpbulk(dstA + 4096u, B_gp + (size_t)(k0 >> 5) * 2048, (uint32_t)rem * 4096u, mbar);
    };

    if (tid == 0) {
        for (int j = 0; j < 3 && j < nIter; j++) issueStage(j);
    }

    // ldsm lane addressing (packed/swizzled layout)
    const int aRow = lrow;                      // 0..15
    const int aSw = (aRow >> 1) & 3;
    const int bRow = wn * 8 + (lane & 7);
    const uint32_t bOff = (uint32_t)(bRow * 64 + (((lane >> 3) ^ ((bRow >> 1) & 3)) << 4));

    for (int it = 0; it < nIter; it++) {
        __syncthreads();
        if (tid == 0 && it + 3 < nIter) issueStage(it + 3);
        const int stage = (u0 + it) & 3;
        mbar_wait(mbarBase + stage * 8, (uint32_t)(((u0 + it) >> 2) & 1));

        const uint32_t sb = smemBase + (uint32_t)stage * STGB;
        const int k0 = it * 128;

#pragma unroll
        for (int sub = 0; sub < 4; sub++) {
            const int kc = k0 + sub * 32;
            if (kc < kend) {
                uint32_t aBase;
                if (kc >= winStart) {
                    aBase = winU + (uint32_t)((kc - winStart) >> 5) * 1024u;
                } else {
                    aBase = sb + (uint32_t)sub * 1024u;
                }
                const uint32_t wB = sb + 4096u + (uint32_t)sub * 4096u;

                uint32_t bh[4];
                ldsm4(bh[0], bh[1], bh[2], bh[3], wB + bOff);
                float* acc = (sub & 1) ? c1 : c0;

#pragma unroll
                for (int kst = 0; kst < 2; kst++) {
                    const int q = kst * 2 + (lane >> 4);
                    const uint32_t aoff = (uint32_t)(aRow * 64 + ((q ^ aSw) << 4));
                    uint32_t a[4];
                    ldsm4(a[0], a[1], a[2], a[3], aBase + aoff);
                    mma_fp16(acc, a, &bh[kst * 2]);
                }
            }
        }
    }
    u = u0 + nIter;

    // ---- epilogue: 4 outputs per warp ----
    const int r0 = lane >> 2;        // 0..7 (and r0+8)
    const int tg = lane & 3;
#pragma unroll
    for (int q = 0; q < 2; q++) {
        int cl = wn * 8 + tg * 2 + q;     // 0..63 window-local col
        int col = wa + cl;
        float bv = bias[col];
        float y0 = fmaxf(c0[q] + c1[q] + bv, 0.f);           // row r0
        float y1 = fmaxf(c0[q + 2] + c1[q + 2] + bv, 0.f);   // row r0+8
        if (outSplit) {
            fp16 h0 = __float2half_rn(y0);
            fp16 h1 = __float2half_rn(y1);
            int kk = col & 31;
            int qp = (kk >> 3) ^ ((r0 >> 1) & 3);
            int e0 = ((cta * 32 + (col >> 5)) * 16) * 32 + r0 * 32 + qp * 8 + (kk & 7);
            gA1p[e0] = h0;
            // row r0+8: swizzle qp' = (kk>>3) ^ (((r0+8)>>1)&3) == qp (since +8 -> +4 in >>1, &3 same? (r0+8)>>1 = r0>>1 + 4; &3 flips bit2 -> same &3? (x+4)&3 == x&3) yes
            gA1p[e0 + 8 * 32] = h1;
            int ew = ((cl >> 5) * 16 + r0) * 32 + qp * 8 + (kk & 7);
            a1w[ew] = h0;
            a1w[ew + 8 * 32] = h1;
        } else {
            a2w[r0 * 65 + cl] = y0;
            a2w[(r0 + 8) * 65 + cl] = y1;
        }
    }
}

// ---------------- lazy pre0 materialization: cols [msA, msA+64) ----------------
__device__ __forceinline__ void materialize(const float* xs, int cta, int msA,
                                            int idx, fp16* p0w) {
    const int tid = (int)threadIdx.x;
    for (int i = tid; i < 1024; i += NT) {
        int r = i & 15;
        int t = msA + (i >> 4);
        const float* wr = g_W0r + t * Dd;
        float acc = g_b0s[t];
        for (int j = 0; j < idx; j++) acc = fmaf(wr[j], xs[r * 33 + j], acc);
        float y = fmaxf(acc, 0.f);
        fp16 hv = __float2half_rn(y);
        int kk = t & 31;
        int qp = (kk >> 3) ^ ((r >> 1) & 3);
        g_p0p[((cta * 32 + (t >> 5)) * 16 + r) * 32 + qp * 8 + (kk & 7)] = hv;
        int cl = t - msA;
        p0w[((cl >> 5) * 16 + r) * 32 + qp * 8 + (kk & 7)] = hv;
    }
}

// ---------------- finish: acc update (new cols only) + outputs ----------------
__device__ __forceinline__ void finish_phase(const float* __restrict__ z,
                                             const float* __restrict__ bout,
                                             float* __restrict__ x,
                                             const float* a2w, float* accS,
                                             float* xs,
                                             int m0, int idx, int h, int hPrev,
                                             int wa) {
    const int tid = (int)threadIdx.x;
    if (h > hPrev) {
#pragma unroll
        for (int k = 0; k < 4; k++) {
            int p = tid + k * NT;          // 0..1023
            int o = p & 63;
            int r = p >> 6;                // 0..15
            float s = 0.f;
            for (int c = hPrev; c < h; c++)
                s = fmaf(a2w[r * 65 + (c - wa)], g_WosT[c * 64 + o], s);
            accS[r * 64 + o] += s;
        }
    }
    __syncthreads();

    const int wid = tid >> 5;
    const int lane = tid & 31;
#pragma unroll
    for (int rr = 0; rr < 2; rr++) {
        int r = wid * 2 + rr;
        if (lane == 0) {
            int row = m0 + r;
            float mu = accS[r * 64 + idx] + bout[idx];
            float ls = accS[r * 64 + idx + Dd] + bout[idx + Dd];
            float xi = z[(size_t)row * Dd + idx] * expf(ls) + mu;
            x[(size_t)row * Dd + idx] = xi;
            xs[r * 33 + idx] = xi;
        }
    }
}

// ---------------- persistent-per-CTA 32-step loop (no inter-CTA sync) -------
__global__ __launch_bounds__(NT, 2) void step_kernel(const float* __restrict__ z,
                                                     const float* __restrict__ bout,
                                                     float* __restrict__ x) {
    extern __shared__ char smraw[];
    const uint32_t smemBase = smem_u32(smraw);
    const uint32_t mbarBase = smemBase + MBAR_OFF;
    fp16* p0w = (fp16*)(smraw + P0W_OFF);
    fp16* a1w = (fp16*)(smraw + A1W_OFF);
    float* a2w = (float*)(smraw + A2W_OFF);
    float* accS = (float*)(smraw + ACC_OFF);
    float* xs = (float*)(smraw + XS_OFF);
    const int cta = (int)blockIdx.x;
    const int m0 = cta * BMs;

    if (threadIdx.x == 0) {
        for (int s = 0; s < 4; s++) mbar_init(mbarBase + s * 8, 1);
    }
    for (int i = threadIdx.x; i < 16 * 64; i += NT) accS[i] = 0.f;
    __syncthreads();

    int u = 0;   // persistent stage-use counter (stage = u&3, parity = (u>>2)&1)

    for (int idx = 0; idx < Dd; idx++) {
        const int h = idx ? (33 * idx + 1) : 0;
        const int hPrev = (idx > 1) ? (33 * (idx - 1) + 1) : 0;
        int wa = 0;
        if (idx) {
            const int msA = hPrev & ~31;
            const int kend1 = msA + 64;        // == (h+31)&~31
            materialize(xs, cta, msA, idx, p0w);
            __syncthreads();
            wa = (h - 33) & ~31;
            if (wa > 960) wa = 960;
            const int jw = wa >> 5;
            // layer 1: A = packed p0 (prefix bulk, fresh cols from p0 window)
            gemm_phase(smemBase, mbarBase, u, smem_u32(p0w), msA,
                       wa, kend1,
                       g_p0p + (size_t)cta * 16384,
                       g_Whp + (size_t)jw * 32 * 2048,
                       g_bhs, 1, g_a1p, a1w, a2w, cta);
            __syncthreads();
            // layer 2: A = packed a1 (prefix bulk, fresh window in smem)
            gemm_phase(smemBase, mbarBase, u, smem_u32(a1w), wa,
                       wa, wa + 64,
                       g_a1p + (size_t)cta * 16384,
                       g_Whp + (size_t)(31 + jw) * 32 * 2048,
                       g_bhs + Hh, 0, nullptr, a1w, a2w, cta);
            __syncthreads();
        }
        finish_phase(z, bout, x, a2w, accS, xs, m0, idx, h, hPrev, wa);
        __syncthreads();
    }
}

// ---------------- launch ----------------
extern "C" void kernel_launch(void* const* d_in, const int* in_sizes, int n_in,
                              void* d_out, int out_size) {
    const float* z    = (const float*)d_in[0];
    const float* W0   = (const float*)d_in[1];
    const float* b0   = (const float*)d_in[2];
    const float* Wh   = (const float*)d_in[3];
    const float* bh   = (const float*)d_in[4];
    const float* Wout = (const float*)d_in[5];
    const float* bout = (const float*)d_in[6];
    float* x = (float*)d_out;

    static int attrSet = 0;
    if (!attrSet) {
        cudaFuncSetAttribute(step_kernel, cudaFuncAttributeMaxDynamicSharedMemorySize,
                             SMEMB);
        attrSet = 1;
    }

    prep_kernel<<<1024, 256>>>(W0, b0, Wh, bh, Wout);
    step_kernel<<<NCTA, NT, SMEMB>>>(z, bout, x);
}